// round 8
// baseline (speedup 1.0000x reference)
#include <cuda_runtime.h>
#include <cstdint>
#include <cstddef>

// Problem shape (fixed for this registry entry)
#define B_ROWS 4096
#define T_LEN  8192
#define K_WIN  5

// ---- pass-1 tiling ----
#define ROWS   32                 // rows per block (one lane per row in LIF/combiner warps)
#define WTILE  128                // timesteps per tile
#define NSTAGE 2                  // ring stages
#define NTILES (T_LEN / WTILE)    // 64
#define GPR    (WTILE / 4)        // 32 float4 per row-tile
#define RSTR   33                 // padded row stride (f4): phase-conflict-free LDS.128

#define X_F4   (NSTAGE * 3 * ROWS * RSTR)   // 6336 f4 = 101.4 KB
#define SP_F4  (NSTAGE * 3 * ROWS * RSTR)   // 6336 f4 = 101.4 KB
#define SMEM_F4 (X_F4 + SP_F4)
#define SMEM_BYTES (SMEM_F4 * 16)           // 202,752 B

__device__ float g_inv[B_ROWS];   // per-row 1/(max+eps) (pass1 -> pass2)

#define PAR(i) ((unsigned)((((unsigned)(i)) >> 1) & 1u))

// ---------------- mbarrier helpers ----------------
__device__ __forceinline__ void mbar_init(unsigned addr, unsigned count) {
    asm volatile("mbarrier.init.shared.b64 [%0], %1;" :: "r"(addr), "r"(count) : "memory");
}
__device__ __forceinline__ void mbar_arrive(unsigned addr) {
    asm volatile("mbarrier.arrive.shared.b64 _, [%0];" :: "r"(addr) : "memory");
}
__device__ __forceinline__ void mbar_wait(unsigned addr, unsigned parity) {
    unsigned done;
    asm volatile("{\n\t.reg .pred p;\n\t"
                 "mbarrier.try_wait.parity.acquire.cta.shared::cta.b64 p, [%1], %2;\n\t"
                 "selp.b32 %0, 1, 0, p;\n\t}"
                 : "=r"(done) : "r"(addr), "r"(parity) : "memory");
    if (!done) {
        asm volatile("{\n\t.reg .pred P1;\n\t"
                     "WL_%=:\n\t"
                     "mbarrier.try_wait.parity.acquire.cta.shared::cta.b64 P1, [%0], %1, 0x989680;\n\t"
                     "@P1 bra.uni WD_%=;\n\t"
                     "bra.uni WL_%=;\n\t"
                     "WD_%=:\n\t}"
                     :: "r"(addr), "r"(parity) : "memory");
    }
}
__device__ __forceinline__ void cp_async16(unsigned smem_addr, const void* gptr) {
    asm volatile("cp.async.cg.shared.global [%0], [%1], 16;" :: "r"(smem_addr), "l"(gptr));
}
__device__ __forceinline__ void cp_async_arrive_noinc(unsigned mbar_addr) {
    asm volatile("cp.async.mbarrier.arrive.noinc.shared.b64 [%0];" :: "r"(mbar_addr) : "memory");
}

// ---------------- top-5 streaming insert (strict > preserves lowest-index ties) ----
__device__ __forceinline__ void top5_insert(float s, int t, float tv[5], int ti[5]) {
    if (s > tv[4]) {
        if (s > tv[0]) {
            tv[4]=tv[3]; ti[4]=ti[3]; tv[3]=tv[2]; ti[3]=ti[2];
            tv[2]=tv[1]; ti[2]=ti[1]; tv[1]=tv[0]; ti[1]=ti[0];
            tv[0]=s; ti[0]=t;
        } else if (s > tv[1]) {
            tv[4]=tv[3]; ti[4]=ti[3]; tv[3]=tv[2]; ti[3]=ti[2];
            tv[2]=tv[1]; ti[2]=ti[1]; tv[1]=s; ti[1]=t;
        } else if (s > tv[2]) {
            tv[4]=tv[3]; ti[4]=ti[3]; tv[3]=tv[2]; ti[3]=ti[2];
            tv[2]=s; ti[2]=t;
        } else if (s > tv[3]) {
            tv[4]=tv[3]; ti[4]=ti[3]; tv[3]=s; ti[3]=t;
        } else {
            tv[4]=s; ti[4]=t;
        }
    }
}

// Exact LIF step, pure float-register chain (no predicates on the recurrence):
//   a = fmaf(d, v, x)                FMA   (lat 4)
//   m = set.ge(a, 1.0) -> 1.0f/0.0f  FSET  (lat 4, alu pipe)
//   v = a - m                        FADD  (lat 4)  [m=1: Sterbenz-exact; m=0: identity]
// m doubles as the spike mask stored to smem — zero extra ops.
__device__ __forceinline__ float lif1(float x, float d, float& v) {
    float a = fmaf(d, v, x);
    float m;
    asm("set.ge.f32.f32 %0, %1, %2;" : "=f"(m) : "f"(a), "f"(1.0f));
    v = a - m;
    return m;
}

// =====================================================================================
// Pass 1 — 8 warps (warp 7 exits):
//   warps 0,4 (SMSP0): fillers — cp.async x tiles (rows 0-15 / 16-31), 2x in-flight
//   warps 1-3        : LIF, one channel each, lane=row, prefetched, conflict-free LDS/STS
//   warp 5 (SMSP1)   : combiner — sal from spike masks, row max, gated top-5, mu/idx/g_inv
//   warp 6 (SMSP2)   : drainer  — recomputes sal from spike masks, coalesced STG
// Barriers per slot s: full(64,cp.async) cdone(96,LIF) sdone(64,comb+drain)
// =====================================================================================
extern "C" __global__ void __launch_bounds__(256, 1)
msa_pass1(const float* __restrict__ amp, const float* __restrict__ pitch,
          const float* __restrict__ bnd, const float* __restrict__ decay,
          const float* __restrict__ weights, float* __restrict__ out)
{
    extern __shared__ float4 smem[];
    float4* smx = smem;            // x tiles
    float4* smp = smem + X_F4;     // spike-mask tiles
    __shared__ __align__(8) unsigned long long s_mb[6];
    unsigned mbar_base = (unsigned)__cvta_generic_to_shared(s_mb);
    // full[s]: s*8 ; cdone[s]: (2+s)*8 ; sdone[s]: (4+s)*8

    const int tid  = threadIdx.x;
    const int lane = tid & 31;
    const int warp = tid >> 5;
    const int b0   = blockIdx.x * ROWS;

    if (tid == 0) {
        #pragma unroll
        for (int s = 0; s < NSTAGE; ++s) {
            mbar_init(mbar_base + (0 + s) * 8, 64);   // full (2 filler warps x 32)
            mbar_init(mbar_base + (2 + s) * 8, 96);   // cdone (3 LIF warps)
            mbar_init(mbar_base + (4 + s) * 8, 64);   // sdone (combiner + drainer)
        }
        asm volatile("fence.proxy.async.shared::cta;" ::: "memory");
    }
    __syncthreads();

    if (warp == 7) return;

    float* out_sal = out + B_ROWS;

    if (warp == 0 || warp == 4) {
        // ---------------- fillers: lane = 16B chunk (0..31), each covers 16 rows ----
        const int cc = lane;
        const int rbase = (warp == 0) ? 0 : 16;
        for (int i = 0; i < NTILES; ++i) {
            const int s = i & 1;
            if (i >= NSTAGE)
                mbar_wait(mbar_base + (2 + s) * 8, PAR(i - 2));   // LIF done with X slot
            #pragma unroll
            for (int c = 0; c < 3; ++c) {
                const float* src = (c == 0) ? amp : (c == 1) ? pitch : bnd;
                float4* dst = smx + (size_t)(s * 3 + c) * ROWS * RSTR;
                #pragma unroll 8
                for (int q = 0; q < 16; ++q) {
                    const int r = rbase + q;
                    unsigned sa = (unsigned)__cvta_generic_to_shared(dst + r * RSTR + cc);
                    cp_async16(sa, src + (size_t)(b0 + r) * T_LEN
                                   + (size_t)i * WTILE + cc * 4);
                }
            }
            cp_async_arrive_noinc(mbar_base + (0 + s) * 8);       // full
        }
    } else if (warp <= 3) {
        // ---------------- LIF warp for channel c: lane = row ----------------
        const int c = warp - 1;
        const int r = lane;
        const float d = __ldg(&decay[c]);
        float v = 0.0f;

        for (int i = 0; i < NTILES; ++i) {
            const int s = i & 1;
            mbar_wait(mbar_base + (0 + s) * 8, PAR(i));           // x ready
            if (i >= NSTAGE)
                mbar_wait(mbar_base + (4 + s) * 8, PAR(i - 2));   // SP slot free

            const float4* X  = smx + ((size_t)(s * 3 + c) * ROWS + r) * RSTR;
            float4*       SP = smp + ((size_t)(s * 3 + c) * ROWS + r) * RSTR;

            float4 nxt = X[0];
            #pragma unroll 8
            for (int g = 0; g < GPR; ++g) {
                const float4 x = nxt;
                if (g + 1 < GPR) nxt = X[g + 1];   // prefetch hides LDS latency
                float4 m;
                m.x = lif1(x.x, d, v);
                m.y = lif1(x.y, d, v);
                m.z = lif1(x.z, d, v);
                m.w = lif1(x.w, d, v);
                SP[g] = m;
            }
            mbar_arrive(mbar_base + (2 + s) * 8);                 // cdone
        }
    } else if (warp == 5) {
        // ---------------- combiner: lane = row; no stores, only max/top-5 ----------
        const int r = lane;
        const float w0 = __ldg(&weights[0]), w1 = __ldg(&weights[1]), w2 = __ldg(&weights[2]);
        float mx = 0.0f;
        float tv[K_WIN] = {-1.0f, -1.0f, -1.0f, -1.0f, -1.0f};
        int   ti[K_WIN] = {0, 0, 0, 0, 0};

        for (int i = 0; i < NTILES; ++i) {
            const int s = i & 1;
            mbar_wait(mbar_base + (2 + s) * 8, PAR(i));           // spikes ready

            const float4* S0 = smp + ((size_t)(s * 3 + 0) * ROWS + r) * RSTR;
            const float4* S1 = smp + ((size_t)(s * 3 + 1) * ROWS + r) * RSTR;
            const float4* S2 = smp + ((size_t)(s * 3 + 2) * ROWS + r) * RSTR;

            float tm = -1.0f;
            #pragma unroll 8
            for (int g = 0; g < GPR; ++g) {
                const float4 m0 = S0[g];
                const float4 m1 = S1[g];
                const float4 m2 = S2[g];
                float4 sv;
                sv.x = fmaf(w2, m2.x, fmaf(w1, m1.x, w0 * m0.x));
                sv.y = fmaf(w2, m2.y, fmaf(w1, m1.y, w0 * m0.y));
                sv.z = fmaf(w2, m2.z, fmaf(w1, m1.z, w0 * m0.z));
                sv.w = fmaf(w2, m2.w, fmaf(w1, m1.w, w0 * m0.w));
                tm = fmaxf(tm, fmaxf(fmaxf(sv.x, sv.y), fmaxf(sv.z, sv.w)));
            }
            mx = fmaxf(mx, tm);

            // Gated rescan: only when this tile beats the current 5th value (rare).
            if (tm > tv[4]) {
                const int tb = i * WTILE;
                for (int g = 0; g < GPR; ++g) {
                    const float4 m0 = S0[g];
                    const float4 m1 = S1[g];
                    const float4 m2 = S2[g];
                    float4 sv;
                    sv.x = fmaf(w2, m2.x, fmaf(w1, m1.x, w0 * m0.x));
                    sv.y = fmaf(w2, m2.y, fmaf(w1, m1.y, w0 * m0.y));
                    sv.z = fmaf(w2, m2.z, fmaf(w1, m1.z, w0 * m0.z));
                    sv.w = fmaf(w2, m2.w, fmaf(w1, m1.w, w0 * m0.w));
                    const int t = tb + g * 4;
                    top5_insert(sv.x, t + 0, tv, ti);
                    top5_insert(sv.y, t + 1, tv, ti);
                    top5_insert(sv.z, t + 2, tv, ti);
                    top5_insert(sv.w, t + 3, tv, ti);
                }
            }
            mbar_arrive(mbar_base + (4 + s) * 8);                 // sdone (1 of 2)
        }

        // ---- row tail: g_inv, mu, topk_idx ----
        const int b = b0 + r;
        const float inv = 1.0f / (mx + 1e-6f);
        g_inv[b] = inv;
        const float n0 = tv[0]*inv, n1 = tv[1]*inv, n2 = tv[2]*inv,
                    n3 = tv[3]*inv, n4 = tv[4]*inv;
        const float avg = ((((n0 + n1) + n2) + n3) + n4) / 5.0f;
        out[b] = 0.5f + 2.0f * tanhf(1.8f * avg);
        float* out_idx = out + B_ROWS + (size_t)B_ROWS * T_LEN;
        #pragma unroll
        for (int k = 0; k < K_WIN; ++k)
            out_idx[(size_t)b * K_WIN + k] = (float)ti[k];
    } else {
        // ---------------- drainer (warp 6): lane = 16B chunk; recompute sal + STG ----
        const int cc = lane;
        const float w0 = __ldg(&weights[0]), w1 = __ldg(&weights[1]), w2 = __ldg(&weights[2]);
        for (int j = 0; j < NTILES; ++j) {
            const int s = j & 1;
            mbar_wait(mbar_base + (2 + s) * 8, PAR(j));           // spikes ready
            const float4* P0 = smp + (size_t)(s * 3 + 0) * ROWS * RSTR;
            const float4* P1 = smp + (size_t)(s * 3 + 1) * ROWS * RSTR;
            const float4* P2 = smp + (size_t)(s * 3 + 2) * ROWS * RSTR;
            #pragma unroll 4
            for (int r = 0; r < ROWS; ++r) {
                const float4 m0 = P0[r * RSTR + cc];
                const float4 m1 = P1[r * RSTR + cc];
                const float4 m2 = P2[r * RSTR + cc];
                float4 sv;
                sv.x = fmaf(w2, m2.x, fmaf(w1, m1.x, w0 * m0.x));
                sv.y = fmaf(w2, m2.y, fmaf(w1, m1.y, w0 * m0.y));
                sv.z = fmaf(w2, m2.z, fmaf(w1, m1.z, w0 * m0.z));
                sv.w = fmaf(w2, m2.w, fmaf(w1, m1.w, w0 * m0.w));
                *reinterpret_cast<float4*>(out_sal + (size_t)(b0 + r) * T_LEN
                                           + (size_t)j * WTILE + cc * 4) = sv;
            }
            mbar_arrive(mbar_base + (4 + s) * 8);                 // sdone (2 of 2)
        }
    }
}

// =====================================================================================
// Pass 2: pure in-place row scale (sal *= g_inv[row]) — streaming, evict-first hints.
// =====================================================================================
extern "C" __global__ void __launch_bounds__(256)
msa_pass2(float4* __restrict__ sal4)
{
    const int i = blockIdx.x * blockDim.x + threadIdx.x;   // one float4 per thread
    const int row = i >> 11;                               // 2048 float4 per row
    const float inv = __ldg(&g_inv[row]);
    float4 v = __ldcs(&sal4[i]);
    v.x *= inv; v.y *= inv; v.z *= inv; v.w *= inv;
    __stcs(&sal4[i], v);
}

extern "C" void kernel_launch(void* const* d_in, const int* in_sizes, int n_in,
                              void* d_out, int out_size) {
    (void)in_sizes; (void)n_in; (void)out_size;
    const float* amp     = (const float*)d_in[0];
    const float* pitch   = (const float*)d_in[1];
    const float* bnd     = (const float*)d_in[2];
    const float* decay   = (const float*)d_in[3];
    const float* weights = (const float*)d_in[4];
    float* out = (float*)d_out;

    cudaFuncSetAttribute(msa_pass1, cudaFuncAttributeMaxDynamicSharedMemorySize, SMEM_BYTES);
    msa_pass1<<<B_ROWS / ROWS, 256, SMEM_BYTES>>>(amp, pitch, bnd, decay, weights, out);

    const int n4 = B_ROWS * (T_LEN / 4);
    msa_pass2<<<n4 / 256, 256>>>(reinterpret_cast<float4*>(out + B_ROWS));
}

// round 9
// speedup vs baseline: 1.1326x; 1.1326x over previous
#include <cuda_runtime.h>
#include <cstdint>
#include <cstddef>

// Problem shape (fixed for this registry entry)
#define B_ROWS 4096
#define T_LEN  8192
#define K_WIN  5

// ---- pass-1 tiling ----
#define ROWS   32                 // rows per block (one lane per row in LIF/combiner warps)
#define WTILE  128                // timesteps per tile
#define NSTAGE 2                  // ring stages
#define NTILES (T_LEN / WTILE)    // 64
#define GPR    (WTILE / 4)        // 32 float4 per row-tile
#define RSTR   33                 // padded row stride (f4): phase-conflict-free LDS.128

#define X_F4   (NSTAGE * 3 * ROWS * RSTR)   // 6336 f4 = 101.4 KB
#define SP_F4  (NSTAGE * 3 * ROWS * RSTR)   // 6336 f4 = 101.4 KB
#define SMEM_F4 (X_F4 + SP_F4)
#define SMEM_BYTES (SMEM_F4 * 16)           // 202,752 B

// Normalization speculation: sal values are exact integers in {0,1,2,3}; rows
// almost surely reach max=3. Drainer stores sal*INV3; combiner records the true
// fixup factor (1.0f when max==3) and a tiny guarded kernel repairs rare rows.
#define INV3 (1.0f / 3.000001f)

__device__ float g_fix[B_ROWS];   // per-row fixup factor (1.0f = stored values already correct)

#define PAR(i) ((unsigned)((((unsigned)(i)) >> 1) & 1u))

// ---------------- mbarrier helpers ----------------
__device__ __forceinline__ void mbar_init(unsigned addr, unsigned count) {
    asm volatile("mbarrier.init.shared.b64 [%0], %1;" :: "r"(addr), "r"(count) : "memory");
}
__device__ __forceinline__ void mbar_arrive(unsigned addr) {
    asm volatile("mbarrier.arrive.shared.b64 _, [%0];" :: "r"(addr) : "memory");
}
__device__ __forceinline__ void mbar_wait(unsigned addr, unsigned parity) {
    unsigned done;
    asm volatile("{\n\t.reg .pred p;\n\t"
                 "mbarrier.try_wait.parity.acquire.cta.shared::cta.b64 p, [%1], %2;\n\t"
                 "selp.b32 %0, 1, 0, p;\n\t}"
                 : "=r"(done) : "r"(addr), "r"(parity) : "memory");
    if (!done) {
        asm volatile("{\n\t.reg .pred P1;\n\t"
                     "WL_%=:\n\t"
                     "mbarrier.try_wait.parity.acquire.cta.shared::cta.b64 P1, [%0], %1, 0x989680;\n\t"
                     "@P1 bra.uni WD_%=;\n\t"
                     "bra.uni WL_%=;\n\t"
                     "WD_%=:\n\t}"
                     :: "r"(addr), "r"(parity) : "memory");
    }
}
__device__ __forceinline__ void cp_async16(unsigned smem_addr, const void* gptr) {
    asm volatile("cp.async.cg.shared.global [%0], [%1], 16;" :: "r"(smem_addr), "l"(gptr));
}
__device__ __forceinline__ void cp_async_arrive_noinc(unsigned mbar_addr) {
    asm volatile("cp.async.mbarrier.arrive.noinc.shared.b64 [%0];" :: "r"(mbar_addr) : "memory");
}

// ---------------- top-5 streaming insert (strict > preserves lowest-index ties) ----
__device__ __forceinline__ void top5_insert(float s, int t, float tv[5], int ti[5]) {
    if (s > tv[4]) {
        if (s > tv[0]) {
            tv[4]=tv[3]; ti[4]=ti[3]; tv[3]=tv[2]; ti[3]=ti[2];
            tv[2]=tv[1]; ti[2]=ti[1]; tv[1]=tv[0]; ti[1]=ti[0];
            tv[0]=s; ti[0]=t;
        } else if (s > tv[1]) {
            tv[4]=tv[3]; ti[4]=ti[3]; tv[3]=tv[2]; ti[3]=ti[2];
            tv[2]=tv[1]; ti[2]=ti[1]; tv[1]=s; ti[1]=t;
        } else if (s > tv[2]) {
            tv[4]=tv[3]; ti[4]=ti[3]; tv[3]=tv[2]; ti[3]=ti[2];
            tv[2]=s; ti[2]=t;
        } else if (s > tv[3]) {
            tv[4]=tv[3]; ti[4]=ti[3]; tv[3]=s; ti[3]=t;
        } else {
            tv[4]=s; ti[4]=t;
        }
    }
}

// Exact LIF step with NO predicates on the recurrence.
// Invariant: a = d*v + x in [0, 1.7). Spike mask m = (a >= 1) computed by
// magic-number round-to-nearest:
//   w = a - (0.5 - 2^-24)        a>=1  =>  w >  0.5 ;  a<1  =>  w <= 0.5
//   y = w + 1.5*2^23 ; m = y - 1.5*2^23   (RN, ulp=1; 0.5-tie rounds EVEN -> m=0)
// All boundary cases verified: a=1.0 -> m=1; a=1-2^-24 -> m=0; a=0 -> m=0.
// v = a - m is EXACT (Sterbenz) -> bitwise identical spikes to prior rounds.
// Chain: FMA(4) + 4x FADD(4) = 20 cyc, all fixed-latency float ops.
__device__ __forceinline__ float lif1(float x, float d, float& v) {
    float a = fmaf(d, v, x);
    float w = a - 0.49999994f;       // 0.5 - 2^-24
    float y = w + 12582912.0f;       // + 1.5*2^23
    float m = y - 12582912.0f;       // exact 0.0f / 1.0f
    v = a - m;
    return m;
}

// =====================================================================================
// Pass 1 — 8 warps (warp 7 exits):
//   warps 0,4 (SMSP0): fillers — cp.async x tiles (rows 0-15 / 16-31), 2x in-flight
//   warps 1-3        : LIF, one channel each, lane=row, prefetched, conflict-free LDS/STS
//   warp 5 (SMSP1)   : combiner — row max, gated top-5, mu/idx, fixup factor
//   warp 6 (SMSP2)   : drainer  — recomputes sal, scales by INV3, coalesced STG
// Barriers per slot s: full(64,cp.async) cdone(96,LIF) sdone(64,comb+drain)
// =====================================================================================
extern "C" __global__ void __launch_bounds__(256, 1)
msa_pass1(const float* __restrict__ amp, const float* __restrict__ pitch,
          const float* __restrict__ bnd, const float* __restrict__ decay,
          const float* __restrict__ weights, float* __restrict__ out)
{
    extern __shared__ float4 smem[];
    float4* smx = smem;            // x tiles
    float4* smp = smem + X_F4;     // spike-mask tiles
    __shared__ __align__(8) unsigned long long s_mb[6];
    unsigned mbar_base = (unsigned)__cvta_generic_to_shared(s_mb);
    // full[s]: s*8 ; cdone[s]: (2+s)*8 ; sdone[s]: (4+s)*8

    const int tid  = threadIdx.x;
    const int lane = tid & 31;
    const int warp = tid >> 5;
    const int b0   = blockIdx.x * ROWS;

    if (tid == 0) {
        #pragma unroll
        for (int s = 0; s < NSTAGE; ++s) {
            mbar_init(mbar_base + (0 + s) * 8, 64);   // full (2 filler warps x 32)
            mbar_init(mbar_base + (2 + s) * 8, 96);   // cdone (3 LIF warps)
            mbar_init(mbar_base + (4 + s) * 8, 64);   // sdone (combiner + drainer)
        }
        asm volatile("fence.proxy.async.shared::cta;" ::: "memory");
    }
    __syncthreads();

    if (warp == 7) return;

    float* out_sal = out + B_ROWS;

    if (warp == 0 || warp == 4) {
        // ---------------- fillers: lane = 16B chunk (0..31), each covers 16 rows ----
        const int cc = lane;
        const int rbase = (warp == 0) ? 0 : 16;
        for (int i = 0; i < NTILES; ++i) {
            const int s = i & 1;
            if (i >= NSTAGE)
                mbar_wait(mbar_base + (2 + s) * 8, PAR(i - 2));   // LIF done with X slot
            #pragma unroll
            for (int c = 0; c < 3; ++c) {
                const float* src = (c == 0) ? amp : (c == 1) ? pitch : bnd;
                float4* dst = smx + (size_t)(s * 3 + c) * ROWS * RSTR;
                #pragma unroll 8
                for (int q = 0; q < 16; ++q) {
                    const int r = rbase + q;
                    unsigned sa = (unsigned)__cvta_generic_to_shared(dst + r * RSTR + cc);
                    cp_async16(sa, src + (size_t)(b0 + r) * T_LEN
                                   + (size_t)i * WTILE + cc * 4);
                }
            }
            cp_async_arrive_noinc(mbar_base + (0 + s) * 8);       // full
        }
    } else if (warp <= 3) {
        // ---------------- LIF warp for channel c: lane = row ----------------
        const int c = warp - 1;
        const int r = lane;
        const float d = __ldg(&decay[c]);
        float v = 0.0f;

        for (int i = 0; i < NTILES; ++i) {
            const int s = i & 1;
            mbar_wait(mbar_base + (0 + s) * 8, PAR(i));           // x ready
            if (i >= NSTAGE)
                mbar_wait(mbar_base + (4 + s) * 8, PAR(i - 2));   // SP slot free

            const float4* X  = smx + ((size_t)(s * 3 + c) * ROWS + r) * RSTR;
            float4*       SP = smp + ((size_t)(s * 3 + c) * ROWS + r) * RSTR;

            float4 nxt = X[0];
            #pragma unroll 8
            for (int g = 0; g < GPR; ++g) {
                const float4 x = nxt;
                if (g + 1 < GPR) nxt = X[g + 1];   // prefetch hides LDS latency
                float4 m;
                m.x = lif1(x.x, d, v);
                m.y = lif1(x.y, d, v);
                m.z = lif1(x.z, d, v);
                m.w = lif1(x.w, d, v);
                SP[g] = m;
            }
            mbar_arrive(mbar_base + (2 + s) * 8);                 // cdone
        }
    } else if (warp == 5) {
        // ---------------- combiner: lane = row; no stores, only max/top-5 ----------
        const int r = lane;
        const float w0 = __ldg(&weights[0]), w1 = __ldg(&weights[1]), w2 = __ldg(&weights[2]);
        float mx = 0.0f;
        float tv[K_WIN] = {-1.0f, -1.0f, -1.0f, -1.0f, -1.0f};
        int   ti[K_WIN] = {0, 0, 0, 0, 0};

        for (int i = 0; i < NTILES; ++i) {
            const int s = i & 1;
            mbar_wait(mbar_base + (2 + s) * 8, PAR(i));           // spikes ready

            const float4* S0 = smp + ((size_t)(s * 3 + 0) * ROWS + r) * RSTR;
            const float4* S1 = smp + ((size_t)(s * 3 + 1) * ROWS + r) * RSTR;
            const float4* S2 = smp + ((size_t)(s * 3 + 2) * ROWS + r) * RSTR;

            float tm = -1.0f;
            #pragma unroll 8
            for (int g = 0; g < GPR; ++g) {
                const float4 m0 = S0[g];
                const float4 m1 = S1[g];
                const float4 m2 = S2[g];
                float4 sv;
                sv.x = fmaf(w2, m2.x, fmaf(w1, m1.x, w0 * m0.x));
                sv.y = fmaf(w2, m2.y, fmaf(w1, m1.y, w0 * m0.y));
                sv.z = fmaf(w2, m2.z, fmaf(w1, m1.z, w0 * m0.z));
                sv.w = fmaf(w2, m2.w, fmaf(w1, m1.w, w0 * m0.w));
                tm = fmaxf(tm, fmaxf(fmaxf(sv.x, sv.y), fmaxf(sv.z, sv.w)));
            }
            mx = fmaxf(mx, tm);

            // Gated rescan: only when this tile beats the current 5th value (rare).
            if (tm > tv[4]) {
                const int tb = i * WTILE;
                for (int g = 0; g < GPR; ++g) {
                    const float4 m0 = S0[g];
                    const float4 m1 = S1[g];
                    const float4 m2 = S2[g];
                    float4 sv;
                    sv.x = fmaf(w2, m2.x, fmaf(w1, m1.x, w0 * m0.x));
                    sv.y = fmaf(w2, m2.y, fmaf(w1, m1.y, w0 * m0.y));
                    sv.z = fmaf(w2, m2.z, fmaf(w1, m1.z, w0 * m0.z));
                    sv.w = fmaf(w2, m2.w, fmaf(w1, m1.w, w0 * m0.w));
                    const int t = tb + g * 4;
                    top5_insert(sv.x, t + 0, tv, ti);
                    top5_insert(sv.y, t + 1, tv, ti);
                    top5_insert(sv.z, t + 2, tv, ti);
                    top5_insert(sv.w, t + 3, tv, ti);
                }
            }
            mbar_arrive(mbar_base + (4 + s) * 8);                 // sdone (1 of 2)
        }

        // ---- row tail: fixup factor, mu, topk_idx ----
        const int b = b0 + r;
        const float inv = 1.0f / (mx + 1e-6f);
        // Drainer stored sal*INV3. If row max != 3, stored rows need rescaling by
        // (3+eps)/(mx+eps); write 1.0f exactly for the (overwhelmingly common) hit.
        g_fix[b] = (mx == 3.0f) ? 1.0f : (3.000001f * inv);
        const float n0 = tv[0]*inv, n1 = tv[1]*inv, n2 = tv[2]*inv,
                    n3 = tv[3]*inv, n4 = tv[4]*inv;
        const float avg = ((((n0 + n1) + n2) + n3) + n4) / 5.0f;
        out[b] = 0.5f + 2.0f * tanhf(1.8f * avg);
        float* out_idx = out + B_ROWS + (size_t)B_ROWS * T_LEN;
        #pragma unroll
        for (int k = 0; k < K_WIN; ++k)
            out_idx[(size_t)b * K_WIN + k] = (float)ti[k];
    } else {
        // -------- drainer (warp 6): lane = 16B chunk; recompute sal, scale, STG ----
        const int cc = lane;
        const float w0 = __ldg(&weights[0]), w1 = __ldg(&weights[1]), w2 = __ldg(&weights[2]);
        for (int j = 0; j < NTILES; ++j) {
            const int s = j & 1;
            mbar_wait(mbar_base + (2 + s) * 8, PAR(j));           // spikes ready
            const float4* P0 = smp + (size_t)(s * 3 + 0) * ROWS * RSTR;
            const float4* P1 = smp + (size_t)(s * 3 + 1) * ROWS * RSTR;
            const float4* P2 = smp + (size_t)(s * 3 + 2) * ROWS * RSTR;
            #pragma unroll 4
            for (int r = 0; r < ROWS; ++r) {
                const float4 m0 = P0[r * RSTR + cc];
                const float4 m1 = P1[r * RSTR + cc];
                const float4 m2 = P2[r * RSTR + cc];
                float4 sv;
                sv.x = fmaf(w2, m2.x, fmaf(w1, m1.x, w0 * m0.x)) * INV3;
                sv.y = fmaf(w2, m2.y, fmaf(w1, m1.y, w0 * m0.y)) * INV3;
                sv.z = fmaf(w2, m2.z, fmaf(w1, m1.z, w0 * m0.z)) * INV3;
                sv.w = fmaf(w2, m2.w, fmaf(w1, m1.w, w0 * m0.w)) * INV3;
                *reinterpret_cast<float4*>(out_sal + (size_t)(b0 + r) * T_LEN
                                           + (size_t)j * WTILE + cc * 4) = sv;
            }
            mbar_arrive(mbar_base + (4 + s) * 8);                 // sdone (2 of 2)
        }
    }
}

// =====================================================================================
// Fixup: one warp per row. Almost always f==1.0f -> immediate exit (~no traffic).
// Rare rows (max != 3) get rescaled in place by f.
// =====================================================================================
extern "C" __global__ void __launch_bounds__(256)
msa_fixup(float* __restrict__ out)
{
    const int warp = threadIdx.x >> 5;
    const int lane = threadIdx.x & 31;
    const int row  = blockIdx.x * 8 + warp;

    const float f = g_fix[row];
    if (f == 1.0f) return;

    float4* sal4 = reinterpret_cast<float4*>(out + B_ROWS) + (size_t)row * (T_LEN / 4);
    for (int it = lane; it < T_LEN / 4; it += 32) {
        float4 v = sal4[it];
        v.x *= f; v.y *= f; v.z *= f; v.w *= f;
        sal4[it] = v;
    }
}

extern "C" void kernel_launch(void* const* d_in, const int* in_sizes, int n_in,
                              void* d_out, int out_size) {
    (void)in_sizes; (void)n_in; (void)out_size;
    const float* amp     = (const float*)d_in[0];
    const float* pitch   = (const float*)d_in[1];
    const float* bnd     = (const float*)d_in[2];
    const float* decay   = (const float*)d_in[3];
    const float* weights = (const float*)d_in[4];
    float* out = (float*)d_out;

    cudaFuncSetAttribute(msa_pass1, cudaFuncAttributeMaxDynamicSharedMemorySize, SMEM_BYTES);
    msa_pass1<<<B_ROWS / ROWS, 256, SMEM_BYTES>>>(amp, pitch, bnd, decay, weights, out);
    msa_fixup<<<B_ROWS / 8, 256>>>(out);
}

// round 10
// speedup vs baseline: 1.2417x; 1.0964x over previous
#include <cuda_runtime.h>
#include <cstdint>
#include <cstddef>

// Problem shape (fixed for this registry entry)
#define B_ROWS 4096
#define T_LEN  8192
#define K_WIN  5

// ---- pass-1 tiling ----
#define ROWS   32                 // rows per block (one lane per row in LIF/combiner warps)
#define WTILE  128                // timesteps per tile
#define NSTAGE 2                  // ring stages
#define NTILES (T_LEN / WTILE)    // 64
#define GPR    (WTILE / 4)        // 32 float4 per row-tile
#define RSTR   33                 // padded row stride (f4): phase-conflict-free LDS.128

#define X_F4   (NSTAGE * 3 * ROWS * RSTR)   // 6336 f4 = 101.4 KB
#define SP_F4  (NSTAGE * 3 * ROWS * RSTR)   // 6336 f4 = 101.4 KB
#define SMEM_F4 (X_F4 + SP_F4)
#define SMEM_BYTES (SMEM_F4 * 16)           // 202,752 B

// Normalization speculation: sal values are exact integers in {0,1,2,3}; rows
// almost surely reach max=3 (verified R9: fixup was a universal fast-path exit).
#define INV3 (1.0f / 3.000001f)

__device__ float g_fix[B_ROWS];   // per-row fixup factor (1.0f = stored values correct)

#define PAR(i) ((unsigned)((((unsigned)(i)) >> 1) & 1u))

// ---------------- mbarrier helpers ----------------
__device__ __forceinline__ void mbar_init(unsigned addr, unsigned count) {
    asm volatile("mbarrier.init.shared.b64 [%0], %1;" :: "r"(addr), "r"(count) : "memory");
}
__device__ __forceinline__ void mbar_arrive(unsigned addr) {
    asm volatile("mbarrier.arrive.shared.b64 _, [%0];" :: "r"(addr) : "memory");
}
__device__ __forceinline__ void mbar_wait(unsigned addr, unsigned parity) {
    unsigned done;
    asm volatile("{\n\t.reg .pred p;\n\t"
                 "mbarrier.try_wait.parity.acquire.cta.shared::cta.b64 p, [%1], %2;\n\t"
                 "selp.b32 %0, 1, 0, p;\n\t}"
                 : "=r"(done) : "r"(addr), "r"(parity) : "memory");
    if (!done) {
        asm volatile("{\n\t.reg .pred P1;\n\t"
                     "WL_%=:\n\t"
                     "mbarrier.try_wait.parity.acquire.cta.shared::cta.b64 P1, [%0], %1, 0x989680;\n\t"
                     "@P1 bra.uni WD_%=;\n\t"
                     "bra.uni WL_%=;\n\t"
                     "WD_%=:\n\t}"
                     :: "r"(addr), "r"(parity) : "memory");
    }
}
__device__ __forceinline__ void cp_async16(unsigned smem_addr, const void* gptr) {
    asm volatile("cp.async.cg.shared.global [%0], [%1], 16;" :: "r"(smem_addr), "l"(gptr));
}
__device__ __forceinline__ void cp_async_arrive_noinc(unsigned mbar_addr) {
    asm volatile("cp.async.mbarrier.arrive.noinc.shared.b64 [%0];" :: "r"(mbar_addr) : "memory");
}

// ---------------- top-5 streaming insert (strict > preserves lowest-index ties) ----
__device__ __forceinline__ void top5_insert(float s, int t, float tv[5], int ti[5]) {
    if (s > tv[4]) {
        if (s > tv[0]) {
            tv[4]=tv[3]; ti[4]=ti[3]; tv[3]=tv[2]; ti[3]=ti[2];
            tv[2]=tv[1]; ti[2]=ti[1]; tv[1]=tv[0]; ti[1]=ti[0];
            tv[0]=s; ti[0]=t;
        } else if (s > tv[1]) {
            tv[4]=tv[3]; ti[4]=ti[3]; tv[3]=tv[2]; ti[3]=ti[2];
            tv[2]=tv[1]; ti[2]=ti[1]; tv[1]=s; ti[1]=t;
        } else if (s > tv[2]) {
            tv[4]=tv[3]; ti[4]=ti[3]; tv[3]=tv[2]; ti[3]=ti[2];
            tv[2]=s; ti[2]=t;
        } else if (s > tv[3]) {
            tv[4]=tv[3]; ti[4]=ti[3]; tv[3]=s; ti[3]=t;
        } else {
            tv[4]=s; ti[4]=t;
        }
    }
}

// Exact LIF step, shortest chain (R7/R8 form, FSETP pred-as-data + FSEL):
//   a = fmaf(d,v,x)  [4] -> { FSETP [4] || u=a-1 [4] } -> v = FSEL(p,u,a) [4]  = 12 cyc
// Spike mask FSEL(p,1,0) hangs off-chain. v update is Sterbenz-exact.
__device__ __forceinline__ float lif1(float x, float d, float& v) {
    float a = fmaf(d, v, x);
    float u = a - 1.0f;
    bool  p = (a >= 1.0f);
    v = p ? u : a;
    return p ? 1.0f : 0.0f;
}

// =====================================================================================
// Pass 1 — 8 warps (warp 3 exits). Role->wid chosen so LIF warps hold the HIGHEST
// wids on their SMSPs (arbiter is hi-wid-first; helpers must not outrank the chain):
//   warp 0 (SMSP0): filler rows 0-15      warp 4 (SMSP0): filler rows 16-31
//   warp 1 (SMSP1): combiner              warp 2 (SMSP2): drainer
//   warp 5 (SMSP1): LIF ch0   warp 6 (SMSP2): LIF ch1   warp 7 (SMSP3): LIF ch2
// Barriers per slot s: full(64,cp.async) cdone(96,LIF) sdone(64,comb+drain)
// =====================================================================================
extern "C" __global__ void __launch_bounds__(256, 1)
msa_pass1(const float* __restrict__ amp, const float* __restrict__ pitch,
          const float* __restrict__ bnd, const float* __restrict__ decay,
          const float* __restrict__ weights, float* __restrict__ out)
{
    extern __shared__ float4 smem[];
    float4* smx = smem;            // x tiles
    float4* smp = smem + X_F4;     // spike-mask tiles
    __shared__ __align__(8) unsigned long long s_mb[6];
    unsigned mbar_base = (unsigned)__cvta_generic_to_shared(s_mb);
    // full[s]: s*8 ; cdone[s]: (2+s)*8 ; sdone[s]: (4+s)*8

    const int tid  = threadIdx.x;
    const int lane = tid & 31;
    const int warp = tid >> 5;
    const int b0   = blockIdx.x * ROWS;

    if (tid == 0) {
        #pragma unroll
        for (int s = 0; s < NSTAGE; ++s) {
            mbar_init(mbar_base + (0 + s) * 8, 64);   // full (2 filler warps x 32)
            mbar_init(mbar_base + (2 + s) * 8, 96);   // cdone (3 LIF warps)
            mbar_init(mbar_base + (4 + s) * 8, 64);   // sdone (combiner + drainer)
        }
        asm volatile("fence.proxy.async.shared::cta;" ::: "memory");
    }
    __syncthreads();

    if (warp == 3) return;

    float* out_sal = out + B_ROWS;

    if (warp == 0 || warp == 4) {
        // ---------------- fillers: lane = 16B chunk (0..31), each covers 16 rows ----
        const int cc = lane;
        const int rbase = (warp == 0) ? 0 : 16;
        for (int i = 0; i < NTILES; ++i) {
            const int s = i & 1;
            if (i >= NSTAGE)
                mbar_wait(mbar_base + (2 + s) * 8, PAR(i - 2));   // LIF done with X slot
            #pragma unroll
            for (int c = 0; c < 3; ++c) {
                const float* src = (c == 0) ? amp : (c == 1) ? pitch : bnd;
                float4* dst = smx + (size_t)(s * 3 + c) * ROWS * RSTR;
                #pragma unroll 8
                for (int q = 0; q < 16; ++q) {
                    const int r = rbase + q;
                    unsigned sa = (unsigned)__cvta_generic_to_shared(dst + r * RSTR + cc);
                    cp_async16(sa, src + (size_t)(b0 + r) * T_LEN
                                   + (size_t)i * WTILE + cc * 4);
                }
            }
            cp_async_arrive_noinc(mbar_base + (0 + s) * 8);       // full
        }
    } else if (warp >= 5) {
        // ---------------- LIF warp for channel c = warp-5: lane = row ----------------
        const int c = warp - 5;
        const int r = lane;
        const float d = __ldg(&decay[c]);
        float v = 0.0f;

        for (int i = 0; i < NTILES; ++i) {
            const int s = i & 1;
            mbar_wait(mbar_base + (0 + s) * 8, PAR(i));           // x ready
            if (i >= NSTAGE)
                mbar_wait(mbar_base + (4 + s) * 8, PAR(i - 2));   // SP slot free

            const float4* X  = smx + ((size_t)(s * 3 + c) * ROWS + r) * RSTR;
            float4*       SP = smp + ((size_t)(s * 3 + c) * ROWS + r) * RSTR;

            float4 nxt = X[0];
            #pragma unroll 8
            for (int g = 0; g < GPR; ++g) {
                const float4 x = nxt;
                if (g + 1 < GPR) nxt = X[g + 1];   // prefetch hides LDS latency
                float4 m;
                m.x = lif1(x.x, d, v);
                m.y = lif1(x.y, d, v);
                m.z = lif1(x.z, d, v);
                m.w = lif1(x.w, d, v);
                SP[g] = m;
            }
            mbar_arrive(mbar_base + (2 + s) * 8);                 // cdone
        }
    } else if (warp == 1) {
        // ---------------- combiner: lane = row; no stores, only max/top-5 ----------
        const int r = lane;
        const float w0 = __ldg(&weights[0]), w1 = __ldg(&weights[1]), w2 = __ldg(&weights[2]);
        float mx = 0.0f;
        float tv[K_WIN] = {-1.0f, -1.0f, -1.0f, -1.0f, -1.0f};
        int   ti[K_WIN] = {0, 0, 0, 0, 0};

        for (int i = 0; i < NTILES; ++i) {
            const int s = i & 1;
            mbar_wait(mbar_base + (2 + s) * 8, PAR(i));           // spikes ready

            const float4* S0 = smp + ((size_t)(s * 3 + 0) * ROWS + r) * RSTR;
            const float4* S1 = smp + ((size_t)(s * 3 + 1) * ROWS + r) * RSTR;
            const float4* S2 = smp + ((size_t)(s * 3 + 2) * ROWS + r) * RSTR;

            float tm = -1.0f;
            #pragma unroll 8
            for (int g = 0; g < GPR; ++g) {
                const float4 m0 = S0[g];
                const float4 m1 = S1[g];
                const float4 m2 = S2[g];
                float4 sv;
                sv.x = fmaf(w2, m2.x, fmaf(w1, m1.x, w0 * m0.x));
                sv.y = fmaf(w2, m2.y, fmaf(w1, m1.y, w0 * m0.y));
                sv.z = fmaf(w2, m2.z, fmaf(w1, m1.z, w0 * m0.z));
                sv.w = fmaf(w2, m2.w, fmaf(w1, m1.w, w0 * m0.w));
                tm = fmaxf(tm, fmaxf(fmaxf(sv.x, sv.y), fmaxf(sv.z, sv.w)));
            }
            mx = fmaxf(mx, tm);

            // Gated rescan: only when this tile beats the current 5th value (rare).
            if (tm > tv[4]) {
                const int tb = i * WTILE;
                for (int g = 0; g < GPR; ++g) {
                    const float4 m0 = S0[g];
                    const float4 m1 = S1[g];
                    const float4 m2 = S2[g];
                    float4 sv;
                    sv.x = fmaf(w2, m2.x, fmaf(w1, m1.x, w0 * m0.x));
                    sv.y = fmaf(w2, m2.y, fmaf(w1, m1.y, w0 * m0.y));
                    sv.z = fmaf(w2, m2.z, fmaf(w1, m1.z, w0 * m0.z));
                    sv.w = fmaf(w2, m2.w, fmaf(w1, m1.w, w0 * m0.w));
                    const int t = tb + g * 4;
                    top5_insert(sv.x, t + 0, tv, ti);
                    top5_insert(sv.y, t + 1, tv, ti);
                    top5_insert(sv.z, t + 2, tv, ti);
                    top5_insert(sv.w, t + 3, tv, ti);
                }
            }
            mbar_arrive(mbar_base + (4 + s) * 8);                 // sdone (1 of 2)
        }

        // ---- row tail: fixup factor, mu, topk_idx ----
        const int b = b0 + r;
        const float inv = 1.0f / (mx + 1e-6f);
        g_fix[b] = (mx == 3.0f) ? 1.0f : (3.000001f * inv);
        const float n0 = tv[0]*inv, n1 = tv[1]*inv, n2 = tv[2]*inv,
                    n3 = tv[3]*inv, n4 = tv[4]*inv;
        const float avg = ((((n0 + n1) + n2) + n3) + n4) / 5.0f;
        out[b] = 0.5f + 2.0f * tanhf(1.8f * avg);
        float* out_idx = out + B_ROWS + (size_t)B_ROWS * T_LEN;
        #pragma unroll
        for (int k = 0; k < K_WIN; ++k)
            out_idx[(size_t)b * K_WIN + k] = (float)ti[k];
    } else {
        // -------- drainer (warp 2): lane = 16B chunk; recompute sal, scale, STG ----
        const int cc = lane;
        const float w0 = __ldg(&weights[0]), w1 = __ldg(&weights[1]), w2 = __ldg(&weights[2]);
        for (int j = 0; j < NTILES; ++j) {
            const int s = j & 1;
            mbar_wait(mbar_base + (2 + s) * 8, PAR(j));           // spikes ready
            const float4* P0 = smp + (size_t)(s * 3 + 0) * ROWS * RSTR;
            const float4* P1 = smp + (size_t)(s * 3 + 1) * ROWS * RSTR;
            const float4* P2 = smp + (size_t)(s * 3 + 2) * ROWS * RSTR;
            #pragma unroll 4
            for (int r = 0; r < ROWS; ++r) {
                const float4 m0 = P0[r * RSTR + cc];
                const float4 m1 = P1[r * RSTR + cc];
                const float4 m2 = P2[r * RSTR + cc];
                float4 sv;
                sv.x = fmaf(w2, m2.x, fmaf(w1, m1.x, w0 * m0.x)) * INV3;
                sv.y = fmaf(w2, m2.y, fmaf(w1, m1.y, w0 * m0.y)) * INV3;
                sv.z = fmaf(w2, m2.z, fmaf(w1, m1.z, w0 * m0.z)) * INV3;
                sv.w = fmaf(w2, m2.w, fmaf(w1, m1.w, w0 * m0.w)) * INV3;
                *reinterpret_cast<float4*>(out_sal + (size_t)(b0 + r) * T_LEN
                                           + (size_t)j * WTILE + cc * 4) = sv;
            }
            mbar_arrive(mbar_base + (4 + s) * 8);                 // sdone (2 of 2)
        }
    }
}

// =====================================================================================
// Fixup: one warp per row. Almost always f==1.0f -> immediate exit.
// =====================================================================================
extern "C" __global__ void __launch_bounds__(256)
msa_fixup(float* __restrict__ out)
{
    const int warp = threadIdx.x >> 5;
    const int lane = threadIdx.x & 31;
    const int row  = blockIdx.x * 8 + warp;

    const float f = g_fix[row];
    if (f == 1.0f) return;

    float4* sal4 = reinterpret_cast<float4*>(out + B_ROWS) + (size_t)row * (T_LEN / 4);
    for (int it = lane; it < T_LEN / 4; it += 32) {
        float4 v = sal4[it];
        v.x *= f; v.y *= f; v.z *= f; v.w *= f;
        sal4[it] = v;
    }
}

// No-op padding kernels: with 5 launches per kernel_launch call, global launch
// index 5 (ncu -s 5 -c 1) lands on msa_pass1 -> pass1 profile becomes visible.
extern "C" __global__ void msa_nop() {}

extern "C" void kernel_launch(void* const* d_in, const int* in_sizes, int n_in,
                              void* d_out, int out_size) {
    (void)in_sizes; (void)n_in; (void)out_size;
    const float* amp     = (const float*)d_in[0];
    const float* pitch   = (const float*)d_in[1];
    const float* bnd     = (const float*)d_in[2];
    const float* decay   = (const float*)d_in[3];
    const float* weights = (const float*)d_in[4];
    float* out = (float*)d_out;

    cudaFuncSetAttribute(msa_pass1, cudaFuncAttributeMaxDynamicSharedMemorySize, SMEM_BYTES);
    msa_pass1<<<B_ROWS / ROWS, 256, SMEM_BYTES>>>(amp, pitch, bnd, decay, weights, out);
    msa_fixup<<<B_ROWS / 8, 256>>>(out);
    msa_nop<<<1, 32>>>();
    msa_nop<<<1, 32>>>();
    msa_nop<<<1, 32>>>();
}

// round 11
// speedup vs baseline: 1.3022x; 1.0487x over previous
#include <cuda_runtime.h>
#include <cstdint>
#include <cstddef>

// Problem shape (fixed for this registry entry)
#define B_ROWS 4096
#define T_LEN  8192
#define K_WIN  5

// ---- pass-1 tiling ----
#define ROWS   32                 // rows per block (one lane per row in LIF/combiner warps)
#define WTILE  64                 // timesteps per tile
#define NTILES (T_LEN / WTILE)    // 128
#define GPR    (WTILE / 4)        // 16 float4 per row-tile
#define RSTR   17                 // padded row stride (f4): conflict-free LDS.128
#define XSTG   4                  // x ring stages
#define SSTG   4                  // spike ring stages

#define X_F4   (XSTG * 3 * ROWS * RSTR)   // 6528 f4 = 104.4 KB
#define SP_F4  (SSTG * 3 * ROWS * RSTR)   // 6528 f4 = 104.4 KB
#define SMEM_F4 (X_F4 + SP_F4)
#define SMEM_BYTES (SMEM_F4 * 16)         // 208,896 B

// Normalization speculation: sal values are exact integers in {0,1,2,3}; rows
// almost surely reach max=3 (verified R9/R10: fixup is a universal fast-path exit).
#define INV3 (1.0f / 3.000001f)

__device__ float g_fix[B_ROWS];   // per-row fixup factor (1.0f = stored values correct)

#define PAR4(i) ((unsigned)((((unsigned)(i)) >> 2) & 1u))

// ---------------- mbarrier helpers ----------------
__device__ __forceinline__ void mbar_init(unsigned addr, unsigned count) {
    asm volatile("mbarrier.init.shared.b64 [%0], %1;" :: "r"(addr), "r"(count) : "memory");
}
__device__ __forceinline__ void mbar_arrive(unsigned addr) {
    asm volatile("mbarrier.arrive.shared.b64 _, [%0];" :: "r"(addr) : "memory");
}
__device__ __forceinline__ void mbar_wait(unsigned addr, unsigned parity) {
    unsigned done;
    asm volatile("{\n\t.reg .pred p;\n\t"
                 "mbarrier.try_wait.parity.acquire.cta.shared::cta.b64 p, [%1], %2;\n\t"
                 "selp.b32 %0, 1, 0, p;\n\t}"
                 : "=r"(done) : "r"(addr), "r"(parity) : "memory");
    if (!done) {
        asm volatile("{\n\t.reg .pred P1;\n\t"
                     "WL_%=:\n\t"
                     "mbarrier.try_wait.parity.acquire.cta.shared::cta.b64 P1, [%0], %1, 0x989680;\n\t"
                     "@P1 bra.uni WD_%=;\n\t"
                     "bra.uni WL_%=;\n\t"
                     "WD_%=:\n\t}"
                     :: "r"(addr), "r"(parity) : "memory");
    }
}
__device__ __forceinline__ void cp_async16(unsigned smem_addr, const void* gptr) {
    asm volatile("cp.async.cg.shared.global [%0], [%1], 16;" :: "r"(smem_addr), "l"(gptr));
}
__device__ __forceinline__ void cp_async_arrive_noinc(unsigned mbar_addr) {
    asm volatile("cp.async.mbarrier.arrive.noinc.shared.b64 [%0];" :: "r"(mbar_addr) : "memory");
}

// ---------------- top-5 streaming insert (strict > preserves lowest-index ties) ----
__device__ __forceinline__ void top5_insert(float s, int t, float tv[5], int ti[5]) {
    if (s > tv[4]) {
        if (s > tv[0]) {
            tv[4]=tv[3]; ti[4]=ti[3]; tv[3]=tv[2]; ti[3]=ti[2];
            tv[2]=tv[1]; ti[2]=ti[1]; tv[1]=tv[0]; ti[1]=ti[0];
            tv[0]=s; ti[0]=t;
        } else if (s > tv[1]) {
            tv[4]=tv[3]; ti[4]=ti[3]; tv[3]=tv[2]; ti[3]=ti[2];
            tv[2]=tv[1]; ti[2]=ti[1]; tv[1]=s; ti[1]=t;
        } else if (s > tv[2]) {
            tv[4]=tv[3]; ti[4]=ti[3]; tv[3]=tv[2]; ti[3]=ti[2];
            tv[2]=s; ti[2]=t;
        } else if (s > tv[3]) {
            tv[4]=tv[3]; ti[4]=ti[3]; tv[3]=s; ti[3]=t;
        } else {
            tv[4]=s; ti[4]=t;
        }
    }
}

// Exact LIF step (R10-verified): FSETP pred-as-data + FSEL, 12-cyc chain.
__device__ __forceinline__ float lif1(float x, float d, float& v) {
    float a = fmaf(d, v, x);
    float u = a - 1.0f;
    bool  p = (a >= 1.0f);
    v = p ? u : a;
    return p ? 1.0f : 0.0f;
}

// =====================================================================================
// Pass 1 — 8 warps (warp 3 exits). LIF warps hold highest wids per SMSP:
//   warp 0 (SMSP0): filler rows 0-15      warp 4 (SMSP0): filler rows 16-31
//   warp 1 (SMSP1): combiner              warp 2 (SMSP2): drainer
//   warp 5 (SMSP1): LIF ch0   warp 6 (SMSP2): LIF ch1   warp 7 (SMSP3): LIF ch2
// Rings: X 4-stage, SP 4-stage (both WTILE=64). Barriers:
//   xfull[4](64,cp.async)  xfree[4](96,LIF)  spdone[4](96,LIF)  spfree[4](64,comb+drain)
// =====================================================================================
extern "C" __global__ void __launch_bounds__(256, 1)
msa_pass1(const float* __restrict__ amp, const float* __restrict__ pitch,
          const float* __restrict__ bnd, const float* __restrict__ decay,
          const float* __restrict__ weights, float* __restrict__ out)
{
    extern __shared__ float4 smem[];
    float4* smx = smem;            // x tiles
    float4* smp = smem + X_F4;     // spike-mask tiles
    __shared__ __align__(8) unsigned long long s_mb[16];
    unsigned mb = (unsigned)__cvta_generic_to_shared(s_mb);
    // xfull[s]: s*8 ; xfree[s]: (4+s)*8 ; spdone[s]: (8+s)*8 ; spfree[s]: (12+s)*8

    const int tid  = threadIdx.x;
    const int lane = tid & 31;
    const int warp = tid >> 5;
    const int b0   = blockIdx.x * ROWS;

    if (tid == 0) {
        #pragma unroll
        for (int s = 0; s < 4; ++s) {
            mbar_init(mb + (0  + s) * 8, 64);   // xfull  (2 filler warps x 32)
            mbar_init(mb + (4  + s) * 8, 96);   // xfree  (3 LIF warps)
            mbar_init(mb + (8  + s) * 8, 96);   // spdone (3 LIF warps)
            mbar_init(mb + (12 + s) * 8, 64);   // spfree (combiner + drainer)
        }
        asm volatile("fence.proxy.async.shared::cta;" ::: "memory");
    }
    __syncthreads();

    if (warp == 3) return;

    float* out_sal = out + B_ROWS;

    if (warp == 0 || warp == 4) {
        // ------- fillers: lane -> (rr = lane>>4, cc = lane&15); 16 rows each -------
        const int rr = lane >> 4;
        const int cc = lane & 15;
        const int rbase = (warp == 0) ? 0 : 16;
        for (int i = 0; i < NTILES; ++i) {
            const int s = i & 3;
            if (i >= XSTG)
                mbar_wait(mb + (4 + s) * 8, PAR4(i - 4));   // x slot free
            #pragma unroll
            for (int c = 0; c < 3; ++c) {
                const float* src = (c == 0) ? amp : (c == 1) ? pitch : bnd;
                float4* dst = smx + (size_t)(s * 3 + c) * ROWS * RSTR;
                #pragma unroll
                for (int q = 0; q < 8; ++q) {
                    const int r = rbase + q * 2 + rr;
                    unsigned sa = (unsigned)__cvta_generic_to_shared(dst + r * RSTR + cc);
                    cp_async16(sa, src + (size_t)(b0 + r) * T_LEN
                                   + (size_t)i * WTILE + cc * 4);
                }
            }
            cp_async_arrive_noinc(mb + (0 + s) * 8);        // xfull
        }
    } else if (warp >= 5) {
        // ---------------- LIF warp for channel c = warp-5: lane = row ----------------
        const int c = warp - 5;
        const int r = lane;
        const float d = __ldg(&decay[c]);
        float v = 0.0f;

        for (int i = 0; i < NTILES; ++i) {
            const int s = i & 3;
            mbar_wait(mb + (0 + s) * 8, PAR4(i));           // x ready
            if (i >= SSTG)
                mbar_wait(mb + (12 + s) * 8, PAR4(i - 4));  // SP slot free

            const float4* X  = smx + ((size_t)(s * 3 + c) * ROWS + r) * RSTR;
            float4*       SP = smp + ((size_t)(s * 3 + c) * ROWS + r) * RSTR;

            float4 nxt = X[0];
            #pragma unroll
            for (int g = 0; g < GPR; ++g) {
                const float4 x = nxt;
                if (g + 1 < GPR) nxt = X[g + 1];   // prefetch hides LDS latency
                float4 m;
                m.x = lif1(x.x, d, v);
                m.y = lif1(x.y, d, v);
                m.z = lif1(x.z, d, v);
                m.w = lif1(x.w, d, v);
                SP[g] = m;
            }
            mbar_arrive(mb + (4 + s) * 8);                  // xfree
            mbar_arrive(mb + (8 + s) * 8);                  // spdone
        }
    } else if (warp == 1) {
        // ---------------- combiner: lane = row; max + gated top-5 ----------------
        const int r = lane;
        const float w0 = __ldg(&weights[0]), w1 = __ldg(&weights[1]), w2 = __ldg(&weights[2]);
        float mx = 0.0f;
        float tv[K_WIN] = {-1.0f, -1.0f, -1.0f, -1.0f, -1.0f};
        int   ti[K_WIN] = {0, 0, 0, 0, 0};

        for (int i = 0; i < NTILES; ++i) {
            const int s = i & 3;
            mbar_wait(mb + (8 + s) * 8, PAR4(i));           // spikes ready

            const float4* S0 = smp + ((size_t)(s * 3 + 0) * ROWS + r) * RSTR;
            const float4* S1 = smp + ((size_t)(s * 3 + 1) * ROWS + r) * RSTR;
            const float4* S2 = smp + ((size_t)(s * 3 + 2) * ROWS + r) * RSTR;

            float tm = -1.0f;
            #pragma unroll
            for (int g = 0; g < GPR; ++g) {
                const float4 m0 = S0[g];
                const float4 m1 = S1[g];
                const float4 m2 = S2[g];
                float4 sv;
                sv.x = fmaf(w2, m2.x, fmaf(w1, m1.x, w0 * m0.x));
                sv.y = fmaf(w2, m2.y, fmaf(w1, m1.y, w0 * m0.y));
                sv.z = fmaf(w2, m2.z, fmaf(w1, m1.z, w0 * m0.z));
                sv.w = fmaf(w2, m2.w, fmaf(w1, m1.w, w0 * m0.w));
                tm = fmaxf(tm, fmaxf(fmaxf(sv.x, sv.y), fmaxf(sv.z, sv.w)));
            }
            mx = fmaxf(mx, tm);

            // Gated rescan: only when this tile beats the current 5th value (rare).
            if (tm > tv[4]) {
                const int tb = i * WTILE;
                for (int g = 0; g < GPR; ++g) {
                    const float4 m0 = S0[g];
                    const float4 m1 = S1[g];
                    const float4 m2 = S2[g];
                    float4 sv;
                    sv.x = fmaf(w2, m2.x, fmaf(w1, m1.x, w0 * m0.x));
                    sv.y = fmaf(w2, m2.y, fmaf(w1, m1.y, w0 * m0.y));
                    sv.z = fmaf(w2, m2.z, fmaf(w1, m1.z, w0 * m0.z));
                    sv.w = fmaf(w2, m2.w, fmaf(w1, m1.w, w0 * m0.w));
                    const int t = tb + g * 4;
                    top5_insert(sv.x, t + 0, tv, ti);
                    top5_insert(sv.y, t + 1, tv, ti);
                    top5_insert(sv.z, t + 2, tv, ti);
                    top5_insert(sv.w, t + 3, tv, ti);
                }
            }
            mbar_arrive(mb + (12 + s) * 8);                 // spfree (1 of 2)
        }

        // ---- row tail: fixup factor, mu, topk_idx ----
        const int b = b0 + r;
        const float inv = 1.0f / (mx + 1e-6f);
        g_fix[b] = (mx == 3.0f) ? 1.0f : (3.000001f * inv);
        const float n0 = tv[0]*inv, n1 = tv[1]*inv, n2 = tv[2]*inv,
                    n3 = tv[3]*inv, n4 = tv[4]*inv;
        const float avg = ((((n0 + n1) + n2) + n3) + n4) / 5.0f;
        out[b] = 0.5f + 2.0f * tanhf(1.8f * avg);
        float* out_idx = out + B_ROWS + (size_t)B_ROWS * T_LEN;
        #pragma unroll
        for (int k = 0; k < K_WIN; ++k)
            out_idx[(size_t)b * K_WIN + k] = (float)ti[k];
    } else {
        // ------- drainer (warp 2): lane -> (rr, cc); recompute sal, scale, STG -------
        const int rr = lane >> 4;
        const int cc = lane & 15;
        const float w0 = __ldg(&weights[0]), w1 = __ldg(&weights[1]), w2 = __ldg(&weights[2]);
        for (int j = 0; j < NTILES; ++j) {
            const int s = j & 3;
            mbar_wait(mb + (8 + s) * 8, PAR4(j));           // spikes ready
            const float4* P0 = smp + (size_t)(s * 3 + 0) * ROWS * RSTR;
            const float4* P1 = smp + (size_t)(s * 3 + 1) * ROWS * RSTR;
            const float4* P2 = smp + (size_t)(s * 3 + 2) * ROWS * RSTR;
            #pragma unroll 4
            for (int q = 0; q < 16; ++q) {
                const int r = q * 2 + rr;
                const float4 m0 = P0[r * RSTR + cc];
                const float4 m1 = P1[r * RSTR + cc];
                const float4 m2 = P2[r * RSTR + cc];
                float4 sv;
                sv.x = fmaf(w2, m2.x, fmaf(w1, m1.x, w0 * m0.x)) * INV3;
                sv.y = fmaf(w2, m2.y, fmaf(w1, m1.y, w0 * m0.y)) * INV3;
                sv.z = fmaf(w2, m2.z, fmaf(w1, m1.z, w0 * m0.z)) * INV3;
                sv.w = fmaf(w2, m2.w, fmaf(w1, m1.w, w0 * m0.w)) * INV3;
                *reinterpret_cast<float4*>(out_sal + (size_t)(b0 + r) * T_LEN
                                           + (size_t)j * WTILE + cc * 4) = sv;
            }
            mbar_arrive(mb + (12 + s) * 8);                 // spfree (2 of 2)
        }
    }
}

// =====================================================================================
// Fixup: 1 thread per row checks g_fix; rescales serially only in the (measure-zero)
// miss path. Hit path: 16 tiny blocks, <1us.
// =====================================================================================
extern "C" __global__ void __launch_bounds__(256)
msa_fixup(float* __restrict__ out)
{
    const int row = blockIdx.x * 256 + threadIdx.x;
    const float f = g_fix[row];
    if (f == 1.0f) return;

    float4* sal4 = reinterpret_cast<float4*>(out + B_ROWS) + (size_t)row * (T_LEN / 4);
    for (int it = 0; it < T_LEN / 4; ++it) {
        float4 v = sal4[it];
        v.x *= f; v.y *= f; v.z *= f; v.w *= f;
        sal4[it] = v;
    }
}

extern "C" void kernel_launch(void* const* d_in, const int* in_sizes, int n_in,
                              void* d_out, int out_size) {
    (void)in_sizes; (void)n_in; (void)out_size;
    const float* amp     = (const float*)d_in[0];
    const float* pitch   = (const float*)d_in[1];
    const float* bnd     = (const float*)d_in[2];
    const float* decay   = (const float*)d_in[3];
    const float* weights = (const float*)d_in[4];
    float* out = (float*)d_out;

    cudaFuncSetAttribute(msa_pass1, cudaFuncAttributeMaxDynamicSharedMemorySize, SMEM_BYTES);
    msa_pass1<<<B_ROWS / ROWS, 256, SMEM_BYTES>>>(amp, pitch, bnd, decay, weights, out);
    msa_fixup<<<B_ROWS / 256, 256>>>(out);
}

// round 12
// speedup vs baseline: 1.3046x; 1.0018x over previous
#include <cuda_runtime.h>
#include <cstdint>
#include <cstddef>

// Problem shape (fixed for this registry entry)
#define B_ROWS 4096
#define T_LEN  8192
#define K_WIN  5

// ---- pass-1 tiling (R10 measured-best geometry) ----
#define ROWS   32                 // rows per block (one lane per row in LIF/combiner warps)
#define WTILE  128                // timesteps per tile
#define NSTAGE 2                  // ring stages
#define NTILES (T_LEN / WTILE)    // 64
#define GPR    (WTILE / 4)        // 32 float4 per row-tile
#define RSTR   33                 // padded row stride (f4): conflict-free LDS.128

#define X_F4   (NSTAGE * 3 * ROWS * RSTR)   // 6336 f4 = 101.4 KB
#define SP_F4  (NSTAGE * 3 * ROWS * RSTR)   // 6336 f4 = 101.4 KB
#define SMEM_F4 (X_F4 + SP_F4)
#define SMEM_BYTES (SMEM_F4 * 16)           // 202,752 B

// Normalization speculation: sal values are exact integers in {0,1,2,3}; rows
// almost surely reach max=3 (verified R9-R11: fixup is a universal fast-path exit).
#define INV3 (1.0f / 3.000001f)

#define PAR(i) ((unsigned)((((unsigned)(i)) >> 1) & 1u))

// ---------------- mbarrier helpers ----------------
__device__ __forceinline__ void mbar_init(unsigned addr, unsigned count) {
    asm volatile("mbarrier.init.shared.b64 [%0], %1;" :: "r"(addr), "r"(count) : "memory");
}
__device__ __forceinline__ void mbar_arrive(unsigned addr) {
    asm volatile("mbarrier.arrive.shared.b64 _, [%0];" :: "r"(addr) : "memory");
}
__device__ __forceinline__ void mbar_wait(unsigned addr, unsigned parity) {
    unsigned done;
    asm volatile("{\n\t.reg .pred p;\n\t"
                 "mbarrier.try_wait.parity.acquire.cta.shared::cta.b64 p, [%1], %2;\n\t"
                 "selp.b32 %0, 1, 0, p;\n\t}"
                 : "=r"(done) : "r"(addr), "r"(parity) : "memory");
    if (!done) {
        asm volatile("{\n\t.reg .pred P1;\n\t"
                     "WL_%=:\n\t"
                     "mbarrier.try_wait.parity.acquire.cta.shared::cta.b64 P1, [%0], %1, 0x989680;\n\t"
                     "@P1 bra.uni WD_%=;\n\t"
                     "bra.uni WL_%=;\n\t"
                     "WD_%=:\n\t}"
                     :: "r"(addr), "r"(parity) : "memory");
    }
}
__device__ __forceinline__ void cp_async16(unsigned smem_addr, const void* gptr) {
    asm volatile("cp.async.cg.shared.global [%0], [%1], 16;" :: "r"(smem_addr), "l"(gptr));
}
__device__ __forceinline__ void cp_async_arrive_noinc(unsigned mbar_addr) {
    asm volatile("cp.async.mbarrier.arrive.noinc.shared.b64 [%0];" :: "r"(mbar_addr) : "memory");
}

// ---------------- top-5 streaming insert (strict > preserves lowest-index ties) ----
__device__ __forceinline__ void top5_insert(float s, int t, float tv[5], int ti[5]) {
    if (s > tv[4]) {
        if (s > tv[0]) {
            tv[4]=tv[3]; ti[4]=ti[3]; tv[3]=tv[2]; ti[3]=ti[2];
            tv[2]=tv[1]; ti[2]=ti[1]; tv[1]=tv[0]; ti[1]=ti[0];
            tv[0]=s; ti[0]=t;
        } else if (s > tv[1]) {
            tv[4]=tv[3]; ti[4]=ti[3]; tv[3]=tv[2]; ti[3]=ti[2];
            tv[2]=tv[1]; ti[2]=ti[1]; tv[1]=s; ti[1]=t;
        } else if (s > tv[2]) {
            tv[4]=tv[3]; ti[4]=ti[3]; tv[3]=tv[2]; ti[3]=ti[2];
            tv[2]=s; ti[2]=t;
        } else if (s > tv[3]) {
            tv[4]=tv[3]; ti[4]=ti[3]; tv[3]=s; ti[3]=t;
        } else {
            tv[4]=s; ti[4]=t;
        }
    }
}

// Exact LIF step (R10-verified): FSETP pred-as-data + FSEL, 12-cyc chain.
__device__ __forceinline__ float lif1(float x, float d, float& v) {
    float a = fmaf(d, v, x);
    float u = a - 1.0f;
    bool  p = (a >= 1.0f);
    v = p ? u : a;
    return p ? 1.0f : 0.0f;
}

// =====================================================================================
// Single fused kernel — 8 warps (warp 3 exits). LIF warps hold highest wids per SMSP:
//   warp 0 (SMSP0): filler rows 0-15      warp 4 (SMSP0): filler rows 16-31
//   warp 1 (SMSP1): combiner              warp 2 (SMSP2): drainer
//   warp 5 (SMSP1): LIF ch0   warp 6 (SMSP2): LIF ch1   warp 7 (SMSP3): LIF ch2
// Barriers per slot s: full(64,cp.async) cdone(96,LIF) sdone(64,comb+drain)
// Epilogue: combiner publishes per-row fix factors in smem; combiner+drainer meet at
// named barrier 7 (64 threads) after the last sal STG and rescale rows in the
// (measure-zero) max!=3 miss path. No second normalization kernel.
// =====================================================================================
extern "C" __global__ void __launch_bounds__(256, 1)
msa_pass1(const float* __restrict__ amp, const float* __restrict__ pitch,
          const float* __restrict__ bnd, const float* __restrict__ decay,
          const float* __restrict__ weights, float* __restrict__ out)
{
    extern __shared__ float4 smem[];
    float4* smx = smem;            // x tiles (reused for fix factors in epilogue)
    float4* smp = smem + X_F4;     // spike-mask tiles
    float*  sfix = reinterpret_cast<float*>(smx);   // 32 floats, safe after LIF finishes
    __shared__ __align__(8) unsigned long long s_mb[6];
    unsigned mb = (unsigned)__cvta_generic_to_shared(s_mb);
    // full[s]: s*8 ; cdone[s]: (2+s)*8 ; sdone[s]: (4+s)*8

    const int tid  = threadIdx.x;
    const int lane = tid & 31;
    const int warp = tid >> 5;
    const int b0   = blockIdx.x * ROWS;

    if (tid == 0) {
        #pragma unroll
        for (int s = 0; s < NSTAGE; ++s) {
            mbar_init(mb + (0 + s) * 8, 64);   // full (2 filler warps x 32)
            mbar_init(mb + (2 + s) * 8, 96);   // cdone (3 LIF warps)
            mbar_init(mb + (4 + s) * 8, 64);   // sdone (combiner + drainer)
        }
        asm volatile("fence.proxy.async.shared::cta;" ::: "memory");
    }
    __syncthreads();

    if (warp == 3) return;

    float* out_sal = out + B_ROWS;

    if (warp == 0 || warp == 4) {
        // ---------------- fillers: lane = 16B chunk (0..31), each covers 16 rows ----
        const int cc = lane;
        const int rbase = (warp == 0) ? 0 : 16;
        for (int i = 0; i < NTILES; ++i) {
            const int s = i & 1;
            if (i >= NSTAGE)
                mbar_wait(mb + (2 + s) * 8, PAR(i - 2));   // LIF done with X slot
            #pragma unroll
            for (int c = 0; c < 3; ++c) {
                const float* src = (c == 0) ? amp : (c == 1) ? pitch : bnd;
                float4* dst = smx + (size_t)(s * 3 + c) * ROWS * RSTR;
                #pragma unroll 8
                for (int q = 0; q < 16; ++q) {
                    const int r = rbase + q;
                    unsigned sa = (unsigned)__cvta_generic_to_shared(dst + r * RSTR + cc);
                    cp_async16(sa, src + (size_t)(b0 + r) * T_LEN
                                   + (size_t)i * WTILE + cc * 4);
                }
            }
            cp_async_arrive_noinc(mb + (0 + s) * 8);       // full
        }
    } else if (warp >= 5) {
        // ---------------- LIF warp for channel c = warp-5: lane = row ----------------
        const int c = warp - 5;
        const int r = lane;
        const float d = __ldg(&decay[c]);
        float v = 0.0f;

        for (int i = 0; i < NTILES; ++i) {
            const int s = i & 1;
            mbar_wait(mb + (0 + s) * 8, PAR(i));           // x ready
            if (i >= NSTAGE)
                mbar_wait(mb + (4 + s) * 8, PAR(i - 2));   // SP slot free

            const float4* X  = smx + ((size_t)(s * 3 + c) * ROWS + r) * RSTR;
            float4*       SP = smp + ((size_t)(s * 3 + c) * ROWS + r) * RSTR;

            float4 nxt = X[0];
            #pragma unroll 8
            for (int g = 0; g < GPR; ++g) {
                const float4 x = nxt;
                if (g + 1 < GPR) nxt = X[g + 1];   // prefetch hides LDS latency
                float4 m;
                m.x = lif1(x.x, d, v);
                m.y = lif1(x.y, d, v);
                m.z = lif1(x.z, d, v);
                m.w = lif1(x.w, d, v);
                SP[g] = m;
            }
            mbar_arrive(mb + (2 + s) * 8);                 // cdone
        }
    } else if (warp == 1) {
        // ---------------- combiner: lane = row; max + gated top-5 ----------------
        const int r = lane;
        const float w0 = __ldg(&weights[0]), w1 = __ldg(&weights[1]), w2 = __ldg(&weights[2]);
        float mx = 0.0f;
        float tv[K_WIN] = {-1.0f, -1.0f, -1.0f, -1.0f, -1.0f};
        int   ti[K_WIN] = {0, 0, 0, 0, 0};

        for (int i = 0; i < NTILES; ++i) {
            const int s = i & 1;
            mbar_wait(mb + (2 + s) * 8, PAR(i));           // spikes ready

            const float4* S0 = smp + ((size_t)(s * 3 + 0) * ROWS + r) * RSTR;
            const float4* S1 = smp + ((size_t)(s * 3 + 1) * ROWS + r) * RSTR;
            const float4* S2 = smp + ((size_t)(s * 3 + 2) * ROWS + r) * RSTR;

            float tm = -1.0f;
            #pragma unroll 8
            for (int g = 0; g < GPR; ++g) {
                const float4 m0 = S0[g];
                const float4 m1 = S1[g];
                const float4 m2 = S2[g];
                float4 sv;
                sv.x = fmaf(w2, m2.x, fmaf(w1, m1.x, w0 * m0.x));
                sv.y = fmaf(w2, m2.y, fmaf(w1, m1.y, w0 * m0.y));
                sv.z = fmaf(w2, m2.z, fmaf(w1, m1.z, w0 * m0.z));
                sv.w = fmaf(w2, m2.w, fmaf(w1, m1.w, w0 * m0.w));
                tm = fmaxf(tm, fmaxf(fmaxf(sv.x, sv.y), fmaxf(sv.z, sv.w)));
            }
            mx = fmaxf(mx, tm);

            // Gated rescan: only when this tile beats the current 5th value (rare).
            if (tm > tv[4]) {
                const int tb = i * WTILE;
                for (int g = 0; g < GPR; ++g) {
                    const float4 m0 = S0[g];
                    const float4 m1 = S1[g];
                    const float4 m2 = S2[g];
                    float4 sv;
                    sv.x = fmaf(w2, m2.x, fmaf(w1, m1.x, w0 * m0.x));
                    sv.y = fmaf(w2, m2.y, fmaf(w1, m1.y, w0 * m0.y));
                    sv.z = fmaf(w2, m2.z, fmaf(w1, m1.z, w0 * m0.z));
                    sv.w = fmaf(w2, m2.w, fmaf(w1, m1.w, w0 * m0.w));
                    const int t = tb + g * 4;
                    top5_insert(sv.x, t + 0, tv, ti);
                    top5_insert(sv.y, t + 1, tv, ti);
                    top5_insert(sv.z, t + 2, tv, ti);
                    top5_insert(sv.w, t + 3, tv, ti);
                }
            }
            mbar_arrive(mb + (4 + s) * 8);                 // sdone (1 of 2)
        }

        // ---- row tail: mu, topk_idx; publish fix factor for epilogue ----
        const int b = b0 + r;
        const float inv = 1.0f / (mx + 1e-6f);
        const float fix = (mx == 3.0f) ? 1.0f : (3.000001f * inv);
        sfix[r] = fix;     // X ring is dead by now (LIF consumed all tiles)
        const float n0 = tv[0]*inv, n1 = tv[1]*inv, n2 = tv[2]*inv,
                    n3 = tv[3]*inv, n4 = tv[4]*inv;
        const float avg = ((((n0 + n1) + n2) + n3) + n4) / 5.0f;
        out[b] = 0.5f + 2.0f * tanhf(1.8f * avg);
        float* out_idx = out + B_ROWS + (size_t)B_ROWS * T_LEN;
        #pragma unroll
        for (int k = 0; k < K_WIN; ++k)
            out_idx[(size_t)b * K_WIN + k] = (float)ti[k];

        // ---- epilogue: meet drainer, rescale own row if needed (measure-zero path) ----
        asm volatile("bar.sync 7, 64;" ::: "memory");
        const float f = sfix[r];
        if (f != 1.0f) {
            float4* row4 = reinterpret_cast<float4*>(out_sal + (size_t)b * T_LEN);
            for (int it = 0; it < T_LEN / 8; ++it) {       // first half of row
                float4 vv = row4[it];
                vv.x *= f; vv.y *= f; vv.z *= f; vv.w *= f;
                row4[it] = vv;
            }
        }
    } else {
        // -------- drainer (warp 2): lane = 16B chunk; recompute sal, scale, STG ----
        const int cc = lane;
        const float w0 = __ldg(&weights[0]), w1 = __ldg(&weights[1]), w2 = __ldg(&weights[2]);
        for (int j = 0; j < NTILES; ++j) {
            const int s = j & 1;
            mbar_wait(mb + (2 + s) * 8, PAR(j));           // spikes ready
            const float4* P0 = smp + (size_t)(s * 3 + 0) * ROWS * RSTR;
            const float4* P1 = smp + (size_t)(s * 3 + 1) * ROWS * RSTR;
            const float4* P2 = smp + (size_t)(s * 3 + 2) * ROWS * RSTR;
            #pragma unroll 4
            for (int r = 0; r < ROWS; ++r) {
                const float4 m0 = P0[r * RSTR + cc];
                const float4 m1 = P1[r * RSTR + cc];
                const float4 m2 = P2[r * RSTR + cc];
                float4 sv;
                sv.x = fmaf(w2, m2.x, fmaf(w1, m1.x, w0 * m0.x)) * INV3;
                sv.y = fmaf(w2, m2.y, fmaf(w1, m1.y, w0 * m0.y)) * INV3;
                sv.z = fmaf(w2, m2.z, fmaf(w1, m1.z, w0 * m0.z)) * INV3;
                sv.w = fmaf(w2, m2.w, fmaf(w1, m1.w, w0 * m0.w)) * INV3;
                __stcs(reinterpret_cast<float4*>(out_sal + (size_t)(b0 + r) * T_LEN
                                                 + (size_t)j * WTILE + cc * 4), sv);
            }
            mbar_arrive(mb + (4 + s) * 8);                 // sdone (2 of 2)
        }

        // ---- epilogue: meet combiner, rescale second half of own row if needed ----
        asm volatile("bar.sync 7, 64;" ::: "memory");
        const int r = lane;
        const float f = sfix[r];
        if (f != 1.0f) {
            float4* row4 = reinterpret_cast<float4*>(out_sal + (size_t)(b0 + r) * T_LEN);
            for (int it = T_LEN / 8; it < T_LEN / 4; ++it) {   // second half of row
                float4 vv = row4[it];
                vv.x *= f; vv.y *= f; vv.z *= f; vv.w *= f;
                row4[it] = vv;
            }
        }
    }
}

extern "C" void kernel_launch(void* const* d_in, const int* in_sizes, int n_in,
                              void* d_out, int out_size) {
    (void)in_sizes; (void)n_in; (void)out_size;
    const float* amp     = (const float*)d_in[0];
    const float* pitch   = (const float*)d_in[1];
    const float* bnd     = (const float*)d_in[2];
    const float* decay   = (const float*)d_in[3];
    const float* weights = (const float*)d_in[4];
    float* out = (float*)d_out;

    cudaFuncSetAttribute(msa_pass1, cudaFuncAttributeMaxDynamicSharedMemorySize, SMEM_BYTES);
    msa_pass1<<<B_ROWS / ROWS, 256, SMEM_BYTES>>>(amp, pitch, bnd, decay, weights, out);
}